// round 2
// baseline (speedup 1.0000x reference)
#include <cuda_runtime.h>
#include <math.h>

// Problem constants (fixed shapes for this instance; top_k = 4)
#define D_MODEL 1024
#define HIDDEN  1024
#define NHEADS  16
#define DHEAD   64
#define NTOK    8192          // B*S = 4*2048
#define SEQ     2048
#define RANK    256
#define TOPK    4
#define NBIG    5248          // 4*1024 (q,k,v,gate) + 16 (decay) + 1024 (outgate) + 112 pad
#define COL_DECAY 4096
#define COL_OGATE 4112
#define NCHUNK  32
#define CHUNKSZ 64

// -------- scratch (device globals: allocation-free rule) --------
__device__ float g_Wbig[D_MODEL * NBIG];          // 21.5 MB
__device__ float g_pre [NTOK * NBIG];             // 172 MB
__device__ float g_kv  [NTOK * HIDDEN];           // 32 MB
__device__ float g_ld  [NTOK * NHEADS];
__device__ float g_out [NTOK * HIDDEN];           // scan output
__device__ float g_y   [NTOK * HIDDEN];           // rms+gated
__device__ float g_Y   [4 * NHEADS * NCHUNK * DHEAD];
__device__ float g_Sin [4 * NHEADS * NCHUNK * DHEAD];
__device__ float g_Adec[4 * NHEADS * NCHUNK];
__device__ float g_opT [HIDDEN * D_MODEL];
__device__ float g_vals[4][TOPK];
__device__ int   g_idx [4][TOPK];

// ---------------- top-k softmax setup ----------------
__global__ void topk_setup(const float* __restrict__ ql, const float* __restrict__ kl,
                           const float* __restrict__ vl, const float* __restrict__ gl)
{
    if (threadIdx.x != 0) return;
    const float* Ls[4] = {ql, kl, vl, gl};
    for (int p = 0; p < 4; p++) {
        float l[16];
        float m = -1e30f;
        for (int i = 0; i < 16; i++) { l[i] = Ls[p][i]; m = fmaxf(m, l[i]); }
        bool used[16] = {false};
        float s = 0.f;
        for (int k = 0; k < TOPK; k++) {
            int best = -1; float bvv = -1e30f;
            for (int i = 0; i < 16; i++)
                if (!used[i] && l[i] > bvv) { bvv = l[i]; best = i; }
            used[best] = true;
            g_idx[p][k] = best;
            float e = expf(l[best] - m);
            g_vals[p][k] = e;
            s += e;
        }
        for (int k = 0; k < TOPK; k++) g_vals[p][k] /= s;
    }
}

// ---------------- generic fp32 GEMM: C = A[M,K] @ B[K,N], row-major, dims % tile == 0 ----------------
__global__ void __launch_bounds__(256) gemm_rrr(
    const float* __restrict__ A, const float* __restrict__ B, float* __restrict__ C,
    int lda, int ldb, int ldc, int K)
{
    __shared__ float As[2][8][128];
    __shared__ float Bs[2][8][128];
    const int tid = threadIdx.x;
    const int tx = tid & 15, ty = tid >> 4;
    const int a_row = tid >> 1, a_quad = (tid & 1) * 4;
    const int b_row = tid >> 5, b_col = (tid & 31) * 4;

    const float* Abase = A + (size_t)(blockIdx.y * 128 + a_row) * lda + a_quad;
    const float* Bbase = B + (size_t)b_row * ldb + blockIdx.x * 128 + b_col;

    float acc[8][8];
#pragma unroll
    for (int i = 0; i < 8; i++)
#pragma unroll
        for (int j = 0; j < 8; j++) acc[i][j] = 0.f;

    float4 av = *(const float4*)(Abase);
    float4 bv = *(const float4*)(Bbase);
    As[0][a_quad + 0][a_row] = av.x;
    As[0][a_quad + 1][a_row] = av.y;
    As[0][a_quad + 2][a_row] = av.z;
    As[0][a_quad + 3][a_row] = av.w;
    *(float4*)&Bs[0][b_row][b_col] = bv;
    __syncthreads();

    const int KT = K >> 3;
    for (int kt = 0; kt < KT; kt++) {
        const int buf = kt & 1;
        if (kt + 1 < KT) {
            av = *(const float4*)(Abase + (kt + 1) * 8);
            bv = *(const float4*)(Bbase + (size_t)(kt + 1) * 8 * ldb);
        }
#pragma unroll
        for (int k = 0; k < 8; k++) {
            float a[8], b[8];
            *(float4*)(a)     = *(const float4*)&As[buf][k][ty * 8];
            *(float4*)(a + 4) = *(const float4*)&As[buf][k][ty * 8 + 4];
            *(float4*)(b)     = *(const float4*)&Bs[buf][k][tx * 8];
            *(float4*)(b + 4) = *(const float4*)&Bs[buf][k][tx * 8 + 4];
#pragma unroll
            for (int i = 0; i < 8; i++)
#pragma unroll
                for (int j = 0; j < 8; j++)
                    acc[i][j] = fmaf(a[i], b[j], acc[i][j]);
        }
        if (kt + 1 < KT) {
            const int nb = buf ^ 1;
            As[nb][a_quad + 0][a_row] = av.x;
            As[nb][a_quad + 1][a_row] = av.y;
            As[nb][a_quad + 2][a_row] = av.z;
            As[nb][a_quad + 3][a_row] = av.w;
            *(float4*)&Bs[nb][b_row][b_col] = bv;
        }
        __syncthreads();
    }

    float* Cp = C + (size_t)(blockIdx.y * 128 + ty * 8) * ldc + blockIdx.x * 128 + tx * 8;
#pragma unroll
    for (int i = 0; i < 8; i++) {
        float4 c0 = make_float4(acc[i][0], acc[i][1], acc[i][2], acc[i][3]);
        float4 c1 = make_float4(acc[i][4], acc[i][5], acc[i][6], acc[i][7]);
        *(float4*)(Cp + (size_t)i * ldc)     = c0;
        *(float4*)(Cp + (size_t)i * ldc + 4) = c1;
    }
}

// ---------------- W_eff builder: W_big[:, p*1024:...] = sum_k vals[p][k] * U[idx] @ V[idx] ----------------
// Treated as GEMM with K = TOPK*RANK = 1024; vals folded into B tile load.
// All global-buffer accesses are device-side symbol references (valid addresses).
__global__ void __launch_bounds__(256) gemm_weff(
    const float* __restrict__ qU, const float* __restrict__ qV,
    const float* __restrict__ kU, const float* __restrict__ kV,
    const float* __restrict__ vU, const float* __restrict__ vV)
{
    __shared__ float As[2][8][128];
    __shared__ float Bs[2][8][128];
    const int p = blockIdx.z;
    const float* U = (p == 0) ? qU : ((p == 1) ? kU : vU);
    const float* V = (p == 0) ? qV : ((p == 1) ? kV : vV);   // gate shares v_U/v_V

    const int tid = threadIdx.x;
    const int tx = tid & 15, ty = tid >> 4;
    const int a_row = tid >> 1, a_quad = (tid & 1) * 4;
    const int b_row = tid >> 5, b_col = (tid & 31) * 4;

    const int mrow = blockIdx.y * 128 + a_row;
    const int ncol = blockIdx.x * 128 + b_col;

    float acc[8][8];
#pragma unroll
    for (int i = 0; i < 8; i++)
#pragma unroll
        for (int j = 0; j < 8; j++) acc[i][j] = 0.f;

    float4 av, bv;
    float val;
    {
        const int prim = g_idx[p][0];
        val = g_vals[p][0];
        av = *(const float4*)(U + (size_t)prim * 262144 + (size_t)mrow * 256 + a_quad);
        bv = *(const float4*)(V + (size_t)prim * 262144 + (size_t)b_row * 1024 + ncol);
    }
    As[0][a_quad + 0][a_row] = av.x;
    As[0][a_quad + 1][a_row] = av.y;
    As[0][a_quad + 2][a_row] = av.z;
    As[0][a_quad + 3][a_row] = av.w;
    {
        float4 t = make_float4(bv.x * val, bv.y * val, bv.z * val, bv.w * val);
        *(float4*)&Bs[0][b_row][b_col] = t;
    }
    __syncthreads();

    const int KT = 128;
    float valn = 0.f;
    for (int kt = 0; kt < KT; kt++) {
        const int buf = kt & 1;
        if (kt + 1 < KT) {
            const int kn = kt + 1;
            const int prim = g_idx[p][kn >> 5];
            valn = g_vals[p][kn >> 5];
            av = *(const float4*)(U + (size_t)prim * 262144 + (size_t)mrow * 256 + ((kn * 8) & 255) + a_quad);
            bv = *(const float4*)(V + (size_t)prim * 262144 + (size_t)(((kn * 8) & 255) + b_row) * 1024 + ncol);
        }
#pragma unroll
        for (int k = 0; k < 8; k++) {
            float a[8], b[8];
            *(float4*)(a)     = *(const float4*)&As[buf][k][ty * 8];
            *(float4*)(a + 4) = *(const float4*)&As[buf][k][ty * 8 + 4];
            *(float4*)(b)     = *(const float4*)&Bs[buf][k][tx * 8];
            *(float4*)(b + 4) = *(const float4*)&Bs[buf][k][tx * 8 + 4];
#pragma unroll
            for (int i = 0; i < 8; i++)
#pragma unroll
                for (int j = 0; j < 8; j++)
                    acc[i][j] = fmaf(a[i], b[j], acc[i][j]);
        }
        if (kt + 1 < KT) {
            const int nb = buf ^ 1;
            As[nb][a_quad + 0][a_row] = av.x;
            As[nb][a_quad + 1][a_row] = av.y;
            As[nb][a_quad + 2][a_row] = av.z;
            As[nb][a_quad + 3][a_row] = av.w;
            float4 t = make_float4(bv.x * valn, bv.y * valn, bv.z * valn, bv.w * valn);
            *(float4*)&Bs[nb][b_row][b_col] = t;
        }
        __syncthreads();
    }

    float* Cp = g_Wbig + (size_t)(blockIdx.y * 128 + ty * 8) * NBIG + p * 1024 + blockIdx.x * 128 + tx * 8;
#pragma unroll
    for (int i = 0; i < 8; i++) {
        float4 c0 = make_float4(acc[i][0], acc[i][1], acc[i][2], acc[i][3]);
        float4 c1 = make_float4(acc[i][4], acc[i][5], acc[i][6], acc[i][7]);
        *(float4*)(Cp + (size_t)i * NBIG)     = c0;
        *(float4*)(Cp + (size_t)i * NBIG + 4) = c1;
    }
}

// ---------------- pack decay_w^T, out_gate_w^T, zero pad into W_big cols [4096, 5248) ----------------
__global__ void pack_extras(const float* __restrict__ decay_w, const float* __restrict__ out_gate_w)
{
    int i = blockIdx.x * 256 + threadIdx.x;
    if (i >= 1024 * 1152) return;
    int d = i / 1152;
    int c = i % 1152;
    float v;
    if (c < 16)        v = decay_w[c * 1024 + d];
    else if (c < 1040) v = out_gate_w[(c - 16) * 1024 + d];
    else               v = 0.f;
    g_Wbig[(size_t)d * NBIG + 4096 + c] = v;
}

// ---------------- transpose out_proj_w [D_MODEL, HIDDEN] -> g_opT [HIDDEN, D_MODEL] ----------------
__global__ void transpose_op(const float* __restrict__ W)
{
    __shared__ float tile[32][33];
    int bx = blockIdx.x * 32, by = blockIdx.y * 32;
#pragma unroll
    for (int j = 0; j < 32; j += 8)
        tile[threadIdx.y + j][threadIdx.x] = W[(size_t)(by + threadIdx.y + j) * 1024 + bx + threadIdx.x];
    __syncthreads();
#pragma unroll
    for (int j = 0; j < 32; j += 8)
        g_opT[(size_t)(bx + threadIdx.y + j) * 1024 + by + threadIdx.x] = tile[threadIdx.x][threadIdx.y + j];
}

// ---------------- pointwise: kv = sigmoid(gate)*k*v ; log_decay = -softplus(pre + b) ----------------
__global__ void pointwise(const float* __restrict__ decay_b)
{
    const int row = blockIdx.y;
    const int col = blockIdx.x * 256 + threadIdx.x;
    const size_t base = (size_t)row * NBIG;
    float kk = g_pre[base + 1024 + col];
    float vv = g_pre[base + 2048 + col];
    float gt = g_pre[base + 3072 + col];
    g_kv[(size_t)row * HIDDEN + col] = kk * vv / (1.f + expf(-gt));
    if (blockIdx.x == 0 && threadIdx.x < NHEADS) {
        float z = g_pre[base + COL_DECAY + threadIdx.x] + decay_b[threadIdx.x];
        float sp = fmaxf(z, 0.f) + log1pf(expf(-fabsf(z)));
        g_ld[row * NHEADS + threadIdx.x] = -sp;
    }
}

// ---------------- chunked scan ----------------
__global__ void scan_pass1()
{
    const int b = blockIdx.z, h = blockIdx.y, c = blockIdx.x, d = threadIdx.x;
    const int row0 = b * SEQ + c * CHUNKSZ;
    float s = 0.f, cum = 0.f;
    for (int t = 0; t < CHUNKSZ; t++) {
        const int row = row0 + t;
        float ld = g_ld[row * NHEADS + h];
        cum += ld;
        s = s * expf(ld) + g_kv[(size_t)row * HIDDEN + h * DHEAD + d];
    }
    const int ci = (b * NHEADS + h) * NCHUNK + c;
    g_Y[ci * DHEAD + d] = s;
    if (d == 0) g_Adec[ci] = expf(cum);
}

__global__ void scan_pass2()
{
    const int h = blockIdx.x, b = blockIdx.y, d = threadIdx.x;
    const int base = (b * NHEADS + h) * NCHUNK;
    float s = 0.f;
    for (int c = 0; c < NCHUNK; c++) {
        g_Sin[(base + c) * DHEAD + d] = s;
        s = g_Adec[base + c] * s + g_Y[(base + c) * DHEAD + d];
    }
}

__global__ void scan_pass3()
{
    const int b = blockIdx.z, h = blockIdx.y, c = blockIdx.x, d = threadIdx.x;
    const int ci = (b * NHEADS + h) * NCHUNK + c;
    const int row0 = b * SEQ + c * CHUNKSZ;
    float s = g_Sin[ci * DHEAD + d];
    for (int t = 0; t < CHUNKSZ; t++) {
        const int row = row0 + t;
        float ld = g_ld[row * NHEADS + h];
        s = s * expf(ld) + g_kv[(size_t)row * HIDDEN + h * DHEAD + d];
        float q = g_pre[(size_t)row * NBIG + h * DHEAD + d];
        g_out[(size_t)row * HIDDEN + h * DHEAD + d] = q * s;
    }
}

// ---------------- RMS-norm + output gate ----------------
__global__ void rms_gate(const float* __restrict__ rms_w)
{
    const int row = blockIdx.x;
    const int tid = threadIdx.x;
    const float* o = g_out + (size_t)row * HIDDEN;
    float ss = 0.f;
    for (int c = tid; c < HIDDEN; c += 256) { float x = o[c]; ss += x * x; }
#pragma unroll
    for (int w = 16; w; w >>= 1) ss += __shfl_xor_sync(0xffffffffu, ss, w);
    __shared__ float red[8];
    if ((tid & 31) == 0) red[tid >> 5] = ss;
    __syncthreads();
    __shared__ float s_rinv;
    if (tid < 8) {
        float v = red[tid];
#pragma unroll
        for (int w = 4; w; w >>= 1) v += __shfl_xor_sync(0xffu, v, w);
        if (tid == 0) s_rinv = rsqrtf(v * (1.f / 1024.f) + 1.1920929e-07f);
    }
    __syncthreads();
    const float rinv = s_rinv;
    for (int c = tid; c < HIDDEN; c += 256) {
        float g = g_pre[(size_t)row * NBIG + COL_OGATE + c];
        g_y[(size_t)row * HIDDEN + c] = o[c] * rinv * rms_w[c] / (1.f + expf(-g));
    }
}

// ---------------- launch ----------------
extern "C" void kernel_launch(void* const* d_in, const int* in_sizes, int n_in,
                              void* d_out, int out_size)
{
    (void)in_sizes; (void)n_in; (void)out_size;
    const float* x    = (const float*)d_in[0];
    const float* qU   = (const float*)d_in[1];
    const float* qV   = (const float*)d_in[2];
    const float* kU   = (const float*)d_in[3];
    const float* kV   = (const float*)d_in[4];
    const float* vU   = (const float*)d_in[5];
    const float* vV   = (const float*)d_in[6];
    const float* ql   = (const float*)d_in[7];
    const float* kl   = (const float*)d_in[8];
    const float* vl   = (const float*)d_in[9];
    const float* gl   = (const float*)d_in[10];
    const float* dw   = (const float*)d_in[11];
    const float* db   = (const float*)d_in[12];
    const float* ogw  = (const float*)d_in[13];
    const float* opw  = (const float*)d_in[14];
    const float* rmsw = (const float*)d_in[15];
    float* out = (float*)d_out;

    // Resolve REAL device addresses of __device__ globals (host-side symbol
    // addresses are invalid as kernel arguments — that was the R1 bug).
    void *p_Wbig = nullptr, *p_pre = nullptr, *p_y = nullptr, *p_opT = nullptr;
    cudaGetSymbolAddress(&p_Wbig, g_Wbig);
    cudaGetSymbolAddress(&p_pre,  g_pre);
    cudaGetSymbolAddress(&p_y,    g_y);
    cudaGetSymbolAddress(&p_opT,  g_opT);
    float* dWbig = (float*)p_Wbig;
    float* dpre  = (float*)p_pre;
    float* dy    = (float*)p_y;
    float* dopT  = (float*)p_opT;

    // 1. top-k softmax weights
    topk_setup<<<1, 32>>>(ql, kl, vl, gl);
    // 2. effective low-rank weights for q/k/v/gate into W_big[:, 0:4096)
    gemm_weff<<<dim3(8, 8, 4), 256>>>(qU, qV, kU, kV, vU, vV);
    // 3. pack decay^T, out_gate^T, zero padding into W_big[:, 4096:5248)
    pack_extras<<<(1024 * 1152 + 255) / 256, 256>>>(dw, ogw);
    // 4. transpose out_proj for the final GEMM
    transpose_op<<<dim3(32, 32), dim3(32, 8)>>>(opw);
    // 5. one fused projection GEMM: pre = x @ W_big   [8192 x 5248]
    gemm_rrr<<<dim3(NBIG / 128, NTOK / 128), 256>>>(x, dWbig, dpre, D_MODEL, NBIG, NBIG, D_MODEL);
    // 6. pointwise kv + log_decay
    pointwise<<<dim3(4, NTOK), 256>>>(db);
    // 7-9. chunked scan
    scan_pass1<<<dim3(NCHUNK, NHEADS, 4), DHEAD>>>();
    scan_pass2<<<dim3(NHEADS, 4), DHEAD>>>();
    scan_pass3<<<dim3(NCHUNK, NHEADS, 4), DHEAD>>>();
    // 10. RMS norm + output gate
    rms_gate<<<NTOK, 256>>>(rmsw);
    // 11. final projection: out = y @ out_proj^T
    gemm_rrr<<<dim3(D_MODEL / 128, NTOK / 128), 256>>>(dy, dopT, out, HIDDEN, D_MODEL, D_MODEL, HIDDEN);
}

// round 4
// speedup vs baseline: 2.6057x; 2.6057x over previous
#include <cuda_runtime.h>
#include <cuda_bf16.h>
#include <math.h>
#include <stdint.h>

// ---------------- problem constants ----------------
#define D_MODEL 1024
#define HIDDEN  1024
#define NHEADS  16
#define DHEAD   64
#define NTOK    8192          // B*S
#define SEQ     2048
#define RANK    256
#define TOPK    4
#define NBIG    5248          // 4*1024 (q,k,v,gate) + 16 (decay) + 1024 (outgate) + 112 pad
#define COL_DECAY 4096
#define COL_OGATE 4112
#define NCHUNK  32
#define CHUNKSZ 64

// ---------------- scratch (device globals; allocation-free rule) ----------------
__device__ __nv_bfloat16 g_xhi [NTOK * D_MODEL];
__device__ __nv_bfloat16 g_xlo [NTOK * D_MODEL];
__device__ __nv_bfloat16 g_WThi[NBIG * D_MODEL];     // W_big^T rows = output features, K-major
__device__ __nv_bfloat16 g_WTlo[NBIG * D_MODEL];
__device__ __nv_bfloat16 g_VThi[4 * HIDDEN * 1024];  // per proj p: VT[o, topk*rank] (weights folded)
__device__ __nv_bfloat16 g_VTlo[4 * HIDDEN * 1024];
__device__ __nv_bfloat16 g_Uchi[4 * D_MODEL * 1024]; // per proj p: U concat [d, topk*rank]
__device__ __nv_bfloat16 g_Uclo[4 * D_MODEL * 1024];
__device__ __nv_bfloat16 g_ophi[D_MODEL * HIDDEN];
__device__ __nv_bfloat16 g_oplo[D_MODEL * HIDDEN];
__device__ __nv_bfloat16 g_yhi [NTOK * HIDDEN];
__device__ __nv_bfloat16 g_ylo [NTOK * HIDDEN];
__device__ float g_pre [NTOK * NBIG];                // fused projection output (fp32)
__device__ float g_kv  [NTOK * HIDDEN];
__device__ float g_ld  [NTOK * NHEADS];
__device__ float g_out [NTOK * HIDDEN];
__device__ float g_Y   [4 * NHEADS * NCHUNK * DHEAD];
__device__ float g_Sin [4 * NHEADS * NCHUNK * DHEAD];
__device__ float g_Adec[4 * NHEADS * NCHUNK];
__device__ float g_vals[4][TOPK];
__device__ int   g_idx [4][TOPK];

// ---------------- helpers ----------------
__device__ __forceinline__ uint32_t smem_u32(const void* p) {
    uint32_t a;
    asm("{ .reg .u64 t; cvta.to.shared.u64 t, %1; cvt.u32.u64 %0, t; }" : "=r"(a) : "l"(p));
    return a;
}
__device__ __forceinline__ uint32_t sw128(uint32_t off) { return off ^ ((off >> 3) & 0x70); }

__device__ __forceinline__ void ldsm4(uint32_t* r, uint32_t addr) {
    asm volatile("ldmatrix.sync.aligned.m8n8.x4.shared.b16 {%0,%1,%2,%3}, [%4];"
        : "=r"(r[0]), "=r"(r[1]), "=r"(r[2]), "=r"(r[3]) : "r"(addr));
}
__device__ __forceinline__ void mma_bf16(float* c, const uint32_t* a, const uint32_t* b) {
    asm volatile("mma.sync.aligned.m16n8k16.row.col.f32.bf16.bf16.f32 "
        "{%0,%1,%2,%3}, {%4,%5,%6,%7}, {%8,%9}, {%0,%1,%2,%3};"
        : "+f"(c[0]), "+f"(c[1]), "+f"(c[2]), "+f"(c[3])
        : "r"(a[0]), "r"(a[1]), "r"(a[2]), "r"(a[3]), "r"(b[0]), "r"(b[1]));
}

// ---------------- chunk loader: 4 tiles (Ahi,Alo,Bhi,Blo) of 128 rows x 64 bf16, SW128 ----------------
__device__ __forceinline__ void load_chunk_cp(
    const __nv_bfloat16* __restrict__ Ahi, const __nv_bfloat16* __restrict__ Alo,
    const __nv_bfloat16* __restrict__ Bhi, const __nv_bfloat16* __restrict__ Blo,
    int K, int mBase, int nBase, int kbase, uint32_t sdst_base, int tid)
{
#pragma unroll
    for (int it = 0; it < 16; it++) {
        int idx = it * 256 + tid;
        int t   = idx >> 10;       // 0:Ahi 1:Alo 2:Bhi 3:Blo (uniform per it)
        int pos = idx & 1023;
        int r   = pos >> 3;
        int c16 = pos & 7;
        const __nv_bfloat16* s =
            (t == 0) ? Ahi + (size_t)(mBase + r) * K :
            (t == 1) ? Alo + (size_t)(mBase + r) * K :
            (t == 2) ? Bhi + (size_t)(nBase + r) * K :
                       Blo + (size_t)(nBase + r) * K;
        s += kbase + c16 * 8;
        uint32_t dst = sdst_base + (uint32_t)t * 16384u + sw128((uint32_t)r * 128u + (uint32_t)c16 * 16u);
        asm volatile("cp.async.cg.shared.global [%0], [%1], 16;" :: "r"(dst), "l"(s) : "memory");
    }
    asm volatile("cp.async.commit_group;" ::: "memory");
}

// ---------------- mma.sync GEMM engine ----------------
// D[128,128] fp32 = sum_K ( Ahi*Bhi + Ahi*Blo + Alo*Bhi ), A[M,K] and B[N,K] K-major bf16.
// 8 warps: wm = wid&1 (2 in M, 64 rows), wn = wid>>1 (4 in N, 32 cols).
// EPI 0: write fp32 C;  EPI 1: write bf16 hi/lo pair (Chi/Clo).
#define SMEM_GEMM (2 * 4 * 16384)

template <int EPI>
__device__ void gemm_tc_body(
    const __nv_bfloat16* __restrict__ Ahi, const __nv_bfloat16* __restrict__ Alo,
    const __nv_bfloat16* __restrict__ Bhi, const __nv_bfloat16* __restrict__ Blo,
    int K, int mBase, int nBase, int mOut,
    float* __restrict__ C, __nv_bfloat16* __restrict__ Chi, __nv_bfloat16* __restrict__ Clo,
    int ldc)
{
    extern __shared__ char smem[];
    const uint32_t sbase = smem_u32(smem);
    const int tid  = threadIdx.x;
    const int wid  = tid >> 5, lane = tid & 31;
    const int wm   = wid & 1,  wn   = wid >> 1;

    float acc[4][4][4];
#pragma unroll
    for (int i = 0; i < 4; i++)
#pragma unroll
        for (int j = 0; j < 4; j++)
#pragma unroll
            for (int q = 0; q < 4; q++) acc[i][j][q] = 0.f;

    const int g = lane >> 3, r = lane & 7;
    // A ldmatrix lane mapping: row block (g&1)*8, col block (g>>1)*8 elems
    const uint32_t a_row  = (uint32_t)(wm * 64 + (g & 1) * 8 + r);
    const uint32_t a_colb = (uint32_t)((g >> 1) * 16);             // bytes
    // B ldmatrix lane mapping: n block (g>>1)*8, k block (g&1)*8 elems
    const uint32_t b_row  = (uint32_t)(wn * 32 + (g >> 1) * 8 + r);
    const uint32_t b_colb = (uint32_t)((g & 1) * 16);              // bytes

    const int NC = K >> 6;
    load_chunk_cp(Ahi, Alo, Bhi, Blo, K, mBase, nBase, 0, sbase, tid);

    for (int c = 0; c < NC; c++) {
        const uint32_t stage = sbase + (uint32_t)(c & 1) * 65536u;
        if (c + 1 < NC) {
            load_chunk_cp(Ahi, Alo, Bhi, Blo, K, mBase, nBase, (c + 1) << 6,
                          sbase + (uint32_t)((c + 1) & 1) * 65536u, tid);
            asm volatile("cp.async.wait_group 1;" ::: "memory");
        } else {
            asm volatile("cp.async.wait_group 0;" ::: "memory");
        }
        __syncthreads();

        const uint32_t Ah = stage, Al = stage + 16384u, Bh = stage + 32768u, Bl = stage + 49152u;
#pragma unroll
        for (int k16 = 0; k16 < 4; k16++) {
            uint32_t ahi[4][4], alo[4][4], bhi[4][2], blo[4][2];
#pragma unroll
            for (int i = 0; i < 4; i++) {
                uint32_t off = sw128((a_row + i * 16) * 128u + (uint32_t)k16 * 32u + a_colb);
                ldsm4(ahi[i], Ah + off);
                ldsm4(alo[i], Al + off);
            }
#pragma unroll
            for (int j2 = 0; j2 < 2; j2++) {
                uint32_t off = sw128((b_row + j2 * 16) * 128u + (uint32_t)k16 * 32u + b_colb);
                uint32_t t[4];
                ldsm4(t, Bh + off);
                bhi[j2 * 2][0] = t[0]; bhi[j2 * 2][1] = t[1];
                bhi[j2 * 2 + 1][0] = t[2]; bhi[j2 * 2 + 1][1] = t[3];
                ldsm4(t, Bl + off);
                blo[j2 * 2][0] = t[0]; blo[j2 * 2][1] = t[1];
                blo[j2 * 2 + 1][0] = t[2]; blo[j2 * 2 + 1][1] = t[3];
            }
#pragma unroll
            for (int i = 0; i < 4; i++)
#pragma unroll
                for (int j = 0; j < 4; j++) {
                    mma_bf16(acc[i][j], ahi[i], bhi[j]);
                    mma_bf16(acc[i][j], ahi[i], blo[j]);
                    mma_bf16(acc[i][j], alo[i], bhi[j]);
                }
        }
        __syncthreads();
    }

    // epilogue
    const int rr = lane >> 2, cc = (lane & 3) * 2;
#pragma unroll
    for (int i = 0; i < 4; i++) {
        const int row = mOut + wm * 64 + i * 16 + rr;
#pragma unroll
        for (int j = 0; j < 4; j++) {
            const int col = nBase + wn * 32 + j * 8 + cc;
            if (EPI == 0) {
                *(float2*)(C + (size_t)row * ldc + col)       = make_float2(acc[i][j][0], acc[i][j][1]);
                *(float2*)(C + (size_t)(row + 8) * ldc + col) = make_float2(acc[i][j][2], acc[i][j][3]);
            } else {
#pragma unroll
                for (int hrow = 0; hrow < 2; hrow++) {
                    float v0 = acc[i][j][hrow * 2], v1 = acc[i][j][hrow * 2 + 1];
                    __nv_bfloat16 h0 = __float2bfloat16_rn(v0), h1 = __float2bfloat16_rn(v1);
                    float l0 = v0 - __bfloat162float(h0), l1 = v1 - __bfloat162float(h1);
                    __nv_bfloat162 hh = __halves2bfloat162(h0, h1);
                    __nv_bfloat162 ll = __halves2bfloat162(__float2bfloat16_rn(l0), __float2bfloat16_rn(l1));
                    const size_t off = (size_t)(row + hrow * 8) * ldc + col;
                    *(uint32_t*)(Chi + off) = *(uint32_t*)&hh;
                    *(uint32_t*)(Clo + off) = *(uint32_t*)&ll;
                }
            }
        }
    }
}

// ---------------- GEMM wrapper kernels ----------------
__global__ void __launch_bounds__(256) k_pre_gemm()
{
    const int mBase = blockIdx.y * 128, nBase = blockIdx.x * 128;
    gemm_tc_body<0>(g_xhi, g_xlo, g_WThi, g_WTlo, D_MODEL, mBase, nBase, mBase,
                    g_pre, nullptr, nullptr, NBIG);
}

__global__ void __launch_bounds__(256) k_weff_gemm()
{
    const int p = blockIdx.z;
    const int mBase = blockIdx.y * 128, nBase = blockIdx.x * 128;
    const size_t off = (size_t)p * 1024 * 1024;
    gemm_tc_body<1>(g_VThi + off, g_VTlo + off, g_Uchi + off, g_Uclo + off,
                    1024, mBase, nBase, p * 1024 + mBase,
                    nullptr, g_WThi, g_WTlo, D_MODEL);
}

__global__ void __launch_bounds__(256) k_final_gemm(float* __restrict__ out)
{
    const int mBase = blockIdx.y * 128, nBase = blockIdx.x * 128;
    gemm_tc_body<0>(g_yhi, g_ylo, g_ophi, g_oplo, HIDDEN, mBase, nBase, mBase,
                    out, nullptr, nullptr, D_MODEL);
}

// ---------------- prep kernels ----------------
__global__ void topk_setup(const float* __restrict__ ql, const float* __restrict__ kl,
                           const float* __restrict__ vl, const float* __restrict__ gl)
{
    if (threadIdx.x != 0) return;
    const float* Ls[4] = {ql, kl, vl, gl};
    for (int p = 0; p < 4; p++) {
        float l[16];
        float m = -1e30f;
        for (int i = 0; i < 16; i++) { l[i] = Ls[p][i]; m = fmaxf(m, l[i]); }
        bool used[16] = {false};
        float s = 0.f;
        for (int k = 0; k < TOPK; k++) {
            int best = -1; float bvv = -1e30f;
            for (int i = 0; i < 16; i++)
                if (!used[i] && l[i] > bvv) { bvv = l[i]; best = i; }
            used[best] = true;
            g_idx[p][k] = best;
            float e = expf(l[best] - m);
            g_vals[p][k] = e;
            s += e;
        }
        for (int k = 0; k < TOPK; k++) g_vals[p][k] /= s;
    }
}

__global__ void conv_pair(const float* __restrict__ src,
                          __nv_bfloat16* __restrict__ hi, __nv_bfloat16* __restrict__ lo, int n)
{
    int i = blockIdx.x * 256 + threadIdx.x;
    if (i >= n) return;
    float v = src[i];
    __nv_bfloat16 h = __float2bfloat16_rn(v);
    hi[i] = h;
    lo[i] = __float2bfloat16_rn(v - __bfloat162float(h));
}

// Uc(p)[d, ks*256+r] = U_p[prim(ks)][d, r]
__global__ void build_Uc(const float* __restrict__ qU, const float* __restrict__ kU,
                         const float* __restrict__ vU)
{
    const int p = blockIdx.y;
    const float* U = (p == 0) ? qU : (p == 1) ? kU : vU;
    int i = blockIdx.x * 256 + threadIdx.x;     // over 1024*1024
    int d = i >> 10, kk = i & 1023, ks = kk >> 8, rr = kk & 255;
    int prim = g_idx[p][ks];
    float v = U[(size_t)prim * (D_MODEL * RANK) + (size_t)d * RANK + rr];
    __nv_bfloat16 h = __float2bfloat16_rn(v);
    size_t off = (size_t)p * 1048576 + i;
    g_Uchi[off] = h;
    g_Uclo[off] = __float2bfloat16_rn(v - __bfloat162float(h));
}

// VT(p)[o, ks*256+r] = vals[p][ks] * V_p[prim(ks)][r, o]
__global__ void build_VT(const float* __restrict__ qV, const float* __restrict__ kV,
                         const float* __restrict__ vV)
{
    __shared__ float tile[32][33];
    const int z = blockIdx.z;            // p*4 + ks
    const int p = z >> 2, ks = z & 3;
    const float* V = (p == 0) ? qV : (p == 1) ? kV : vV;
    const int prim = g_idx[p][ks];
    const float w = g_vals[p][ks];
    const float* Vp = V + (size_t)prim * (RANK * HIDDEN);
    const int r0 = blockIdx.x * 32, o0 = blockIdx.y * 32;
#pragma unroll
    for (int j = 0; j < 32; j += 8)
        tile[threadIdx.y + j][threadIdx.x] = Vp[(size_t)(r0 + threadIdx.y + j) * HIDDEN + o0 + threadIdx.x];
    __syncthreads();
#pragma unroll
    for (int j = 0; j < 32; j += 8) {
        float v = w * tile[threadIdx.x][threadIdx.y + j];
        size_t off = (size_t)p * 1048576 + (size_t)(o0 + threadIdx.y + j) * 1024 + ks * 256 + r0 + threadIdx.x;
        __nv_bfloat16 h = __float2bfloat16_rn(v);
        g_VThi[off] = h;
        g_VTlo[off] = __float2bfloat16_rn(v - __bfloat162float(h));
    }
}

// W_bigT rows 4096..5247: decay_w rows, out_gate_w rows, zero pad
__global__ void pack_tail(const float* __restrict__ dw, const float* __restrict__ ogw)
{
    int i = blockIdx.x * 256 + threadIdx.x;     // over 1152*1024
    if (i >= 1152 * 1024) return;
    int rr = i >> 10, d = i & 1023;
    float v = 0.f;
    if (rr < 16)             v = dw[rr * D_MODEL + d];
    else if (rr < 16 + 1024) v = ogw[(rr - 16) * D_MODEL + d];
    size_t off = (size_t)(4096 + rr) * D_MODEL + d;
    __nv_bfloat16 h = __float2bfloat16_rn(v);
    g_WThi[off] = h;
    g_WTlo[off] = __float2bfloat16_rn(v - __bfloat162float(h));
}

// ---------------- pointwise: kv = sigmoid(gate)*k*v ; log_decay = -softplus(pre + b) ----------------
__global__ void pointwise(const float* __restrict__ decay_b)
{
    const int row = blockIdx.y;
    const int col = blockIdx.x * 256 + threadIdx.x;
    const size_t base = (size_t)row * NBIG;
    float kk = g_pre[base + 1024 + col];
    float vv = g_pre[base + 2048 + col];
    float gt = g_pre[base + 3072 + col];
    g_kv[(size_t)row * HIDDEN + col] = kk * vv / (1.f + expf(-gt));
    if (blockIdx.x == 0 && threadIdx.x < NHEADS) {
        float z = g_pre[base + COL_DECAY + threadIdx.x] + decay_b[threadIdx.x];
        float sp = fmaxf(z, 0.f) + log1pf(expf(-fabsf(z)));
        g_ld[row * NHEADS + threadIdx.x] = -sp;
    }
}

// ---------------- chunked scan ----------------
__global__ void scan_pass1()
{
    const int b = blockIdx.z, h = blockIdx.y, c = blockIdx.x, d = threadIdx.x;
    const int row0 = b * SEQ + c * CHUNKSZ;
    float s = 0.f, cum = 0.f;
    for (int t = 0; t < CHUNKSZ; t++) {
        const int row = row0 + t;
        float ld = g_ld[row * NHEADS + h];
        cum += ld;
        s = s * expf(ld) + g_kv[(size_t)row * HIDDEN + h * DHEAD + d];
    }
    const int ci = (b * NHEADS + h) * NCHUNK + c;
    g_Y[ci * DHEAD + d] = s;
    if (d == 0) g_Adec[ci] = expf(cum);
}

__global__ void scan_pass2()
{
    const int h = blockIdx.x, b = blockIdx.y, d = threadIdx.x;
    const int base = (b * NHEADS + h) * NCHUNK;
    float s = 0.f;
    for (int c = 0; c < NCHUNK; c++) {
        g_Sin[(base + c) * DHEAD + d] = s;
        s = g_Adec[base + c] * s + g_Y[(base + c) * DHEAD + d];
    }
}

__global__ void scan_pass3()
{
    const int b = blockIdx.z, h = blockIdx.y, c = blockIdx.x, d = threadIdx.x;
    const int ci = (b * NHEADS + h) * NCHUNK + c;
    const int row0 = b * SEQ + c * CHUNKSZ;
    float s = g_Sin[ci * DHEAD + d];
    for (int t = 0; t < CHUNKSZ; t++) {
        const int row = row0 + t;
        float ld = g_ld[row * NHEADS + h];
        s = s * expf(ld) + g_kv[(size_t)row * HIDDEN + h * DHEAD + d];
        float q = g_pre[(size_t)row * NBIG + h * DHEAD + d];
        g_out[(size_t)row * HIDDEN + h * DHEAD + d] = q * s;
    }
}

// ---------------- RMS-norm + output gate -> bf16 pair for final GEMM ----------------
__global__ void rms_gate(const float* __restrict__ rms_w)
{
    const int row = blockIdx.x;
    const int tid = threadIdx.x;
    const float* o = g_out + (size_t)row * HIDDEN;
    float ss = 0.f;
    for (int c = tid; c < HIDDEN; c += 256) { float x = o[c]; ss += x * x; }
#pragma unroll
    for (int w = 16; w; w >>= 1) ss += __shfl_xor_sync(0xffffffffu, ss, w);
    __shared__ float red[8];
    if ((tid & 31) == 0) red[tid >> 5] = ss;
    __syncthreads();
    __shared__ float s_rinv;
    if (tid < 8) {
        float v = red[tid];
#pragma unroll
        for (int w = 4; w; w >>= 1) v += __shfl_xor_sync(0xffu, v, w);
        if (tid == 0) s_rinv = rsqrtf(v * (1.f / 1024.f) + 1.1920929e-07f);
    }
    __syncthreads();
    const float rinv = s_rinv;
    for (int c = tid; c < HIDDEN; c += 256) {
        float g = g_pre[(size_t)row * NBIG + COL_OGATE + c];
        float y = o[c] * rinv * rms_w[c] / (1.f + expf(-g));
        __nv_bfloat16 h = __float2bfloat16_rn(y);
        size_t off = (size_t)row * HIDDEN + c;
        g_yhi[off] = h;
        g_ylo[off] = __float2bfloat16_rn(y - __bfloat162float(h));
    }
}

// ---------------- launch ----------------
extern "C" void kernel_launch(void* const* d_in, const int* in_sizes, int n_in,
                              void* d_out, int out_size)
{
    (void)in_sizes; (void)n_in; (void)out_size;
    const float* x    = (const float*)d_in[0];
    const float* qU   = (const float*)d_in[1];
    const float* qV   = (const float*)d_in[2];
    const float* kU   = (const float*)d_in[3];
    const float* kV   = (const float*)d_in[4];
    const float* vU   = (const float*)d_in[5];
    const float* vV   = (const float*)d_in[6];
    const float* ql   = (const float*)d_in[7];
    const float* kl   = (const float*)d_in[8];
    const float* vl   = (const float*)d_in[9];
    const float* gl   = (const float*)d_in[10];
    const float* dw   = (const float*)d_in[11];
    const float* db   = (const float*)d_in[12];
    const float* ogw  = (const float*)d_in[13];
    const float* opw  = (const float*)d_in[14];
    const float* rmsw = (const float*)d_in[15];
    float* out = (float*)d_out;

    void *p_xhi, *p_xlo, *p_ophi, *p_oplo;
    cudaGetSymbolAddress(&p_xhi,  g_xhi);
    cudaGetSymbolAddress(&p_xlo,  g_xlo);
    cudaGetSymbolAddress(&p_ophi, g_ophi);
    cudaGetSymbolAddress(&p_oplo, g_oplo);

    cudaFuncSetAttribute(k_pre_gemm,   cudaFuncAttributeMaxDynamicSharedMemorySize, SMEM_GEMM);
    cudaFuncSetAttribute(k_weff_gemm,  cudaFuncAttributeMaxDynamicSharedMemorySize, SMEM_GEMM);
    cudaFuncSetAttribute(k_final_gemm, cudaFuncAttributeMaxDynamicSharedMemorySize, SMEM_GEMM);

    // prep: fp32 -> bf16 hi/lo
    conv_pair<<<(NTOK * D_MODEL + 255) / 256, 256>>>(x, (__nv_bfloat16*)p_xhi, (__nv_bfloat16*)p_xlo, NTOK * D_MODEL);
    conv_pair<<<(D_MODEL * HIDDEN + 255) / 256, 256>>>(opw, (__nv_bfloat16*)p_ophi, (__nv_bfloat16*)p_oplo, D_MODEL * HIDDEN);
    // top-k softmax weights
    topk_setup<<<1, 32>>>(ql, kl, vl, gl);
    // gather/convert selected bank operands
    build_Uc<<<dim3(4096, 4), 256>>>(qU, kU, vU);
    build_VT<<<dim3(8, 32, 16), dim3(32, 8)>>>(qV, kV, vV);
    // W_effT for q/k/v/gate -> W_bigT rows [0,4096)
    k_weff_gemm<<<dim3(8, 8, 4), 256, SMEM_GEMM>>>();
    // decay/out_gate/pad rows -> W_bigT rows [4096,5248)
    pack_tail<<<(1152 * 1024 + 255) / 256, 256>>>(dw, ogw);
    // fused projection GEMM: pre = x @ W_big
    k_pre_gemm<<<dim3(NBIG / 128, NTOK / 128), 256, SMEM_GEMM>>>();
    // pointwise kv + log_decay
    pointwise<<<dim3(4, NTOK), 256>>>(db);
    // chunked scan
    scan_pass1<<<dim3(NCHUNK, NHEADS, 4), DHEAD>>>();
    scan_pass2<<<dim3(NHEADS, 4), DHEAD>>>();
    scan_pass3<<<dim3(NCHUNK, NHEADS, 4), DHEAD>>>();
    // RMS norm + output gate (-> bf16 pair)
    rms_gate<<<NTOK, 256>>>(rmsw);
    // final projection
    k_final_gemm<<<dim3(D_MODEL / 128, NTOK / 128), 256, SMEM_GEMM>>>(out);
}